// round 15
// baseline (speedup 1.0000x reference)
#include <cuda_runtime.h>

#define EMB 1024
#define DKH 64
#define NB 4
#define SL 4096
#define MTOT (NB*SL)
#define NSPLIT 2
#define TPS (SL/64/NSPLIT)     // key tiles per split = 32

// ---------------- scratch (no allocations allowed) ----------------
// Q/K/V stored as tf32 bits, d-transposed within each 64-wide row:
//   element (row, d) lives at word  row*64 + (d%8)*8 + d/8
__device__ unsigned g_Q[MTOT*DKH];
__device__ unsigned g_K[MTOT*DKH];
__device__ unsigned g_V[MTOT*DKH];
__device__ float    g_part[(size_t)NSPLIT*MTOT*DKH];  // unnormalized partial O
__device__ float    g_ml[(size_t)NSPLIT*MTOT*2];      // (m, l) per split per row

// ---------------- helpers ----------------
__device__ __forceinline__ unsigned f2tf(float f){
    unsigned u; asm("cvt.rna.tf32.f32 %0, %1;" : "=r"(u) : "f"(f)); return u;
}
__device__ __forceinline__ float ex2(float x){
    float y; asm("ex2.approx.ftz.f32 %0, %1;" : "=f"(y) : "f"(x)); return y;
}
__device__ __forceinline__ void mma8(float* c,
        unsigned a0, unsigned a1, unsigned a2, unsigned a3,
        unsigned b0, unsigned b1){
    asm volatile(
        "mma.sync.aligned.m16n8k8.row.col.f32.tf32.tf32.f32 "
        "{%0,%1,%2,%3},{%4,%5,%6,%7},{%8,%9},{%0,%1,%2,%3};"
        : "+f"(c[0]), "+f"(c[1]), "+f"(c[2]), "+f"(c[3])
        : "r"(a0), "r"(a1), "r"(a2), "r"(a3), "r"(b0), "r"(b1));
}
__device__ __forceinline__ void cpa16(unsigned* s, const unsigned* g){
    asm volatile("cp.async.cg.shared.global [%0], [%1], 16;"
        :: "r"((unsigned)__cvta_generic_to_shared(s)), "l"(g));
}

// 64-row-tile epilogue: bias + scale, tf32 convert, d-transposed layout.
// Warp layout 2x4: rows wm*32+i*16+{g,g+8}, cols wn*16 + j*8 + 2tg (+1).
// word(row, d) = row*64 + (d%8)*8 + d/8  ->  16tg + 2wn + j (+8 for odd d).
__device__ __forceinline__ void store_proj64(unsigned* out, float acc[2][2][4],
        const float* __restrict__ bias, float scale,
        int row0, int wm, int wn, int g, int tg)
{
    const int c0 = wn*16 + 2*tg;        // j=0 even col
    const int c1 = c0 + 8;              // j=1 even col
    const float b00 = bias[c0], b01 = bias[c0+1];
    const float b10 = bias[c1], b11 = bias[c1+1];
    const int w = 16*tg + 2*wn;
    #pragma unroll
    for (int i = 0; i < 2; i++) {
        int r = row0 + wm*32 + i*16 + g;
        uint2 lo0 = make_uint2(f2tf((acc[i][0][0] + b00) * scale),
                               f2tf((acc[i][1][0] + b10) * scale));
        uint2 hi0 = make_uint2(f2tf((acc[i][0][1] + b01) * scale),
                               f2tf((acc[i][1][1] + b11) * scale));
        *(uint2*)(out + (size_t)r*DKH + w)     = lo0;
        *(uint2*)(out + (size_t)r*DKH + w + 8) = hi0;
        uint2 lo1 = make_uint2(f2tf((acc[i][0][2] + b00) * scale),
                               f2tf((acc[i][1][2] + b10) * scale));
        uint2 hi1 = make_uint2(f2tf((acc[i][0][3] + b01) * scale),
                               f2tf((acc[i][1][3] + b11) * scale));
        *(uint2*)(out + (size_t)(r+8)*DKH + w)     = lo1;
        *(uint2*)(out + (size_t)(r+8)*DKH + w + 8) = hi1;
    }
}

// ============================================================================
// Kernel 1a: Q projection, 64-row tiles.  grid = MTOT/64 = 256 CTAs.
// Register-prefetch pipeline (validated).  Scale = 1/8 * log2(e).
// ============================================================================
__global__ __launch_bounds__(256) void proj_q64(
    const float* __restrict__ in2,
    const float* __restrict__ Wq, const float* __restrict__ bq)
{
    __shared__ unsigned As[64*36];
    __shared__ unsigned Bs[32*72];

    const int tid = threadIdx.x;
    const int lane = tid & 31, wid = tid >> 5;
    const int g = lane >> 2, tg = lane & 3;
    const int wm = wid & 1, wn = wid >> 1;      // 2 x 4 warps over 64x64
    const int row0 = blockIdx.x * 64;

    const int ar = tid >> 3,  ac = (tid & 7) * 4;    // + i*32 rows (A: 64x32)
    const int br = tid >> 4,  bc = (tid & 15) * 4;   // + i*16 rows (B: 32x64)

    float acc[2][2][4];
    #pragma unroll
    for (int i = 0; i < 2; i++)
        #pragma unroll
        for (int j = 0; j < 2; j++)
            #pragma unroll
            for (int e = 0; e < 4; e++) acc[i][j][e] = 0.f;

    float4 Ar[2], Br[2];
    #pragma unroll
    for (int i = 0; i < 2; i++)
        Ar[i] = *(const float4*)(in2 + (size_t)(row0 + ar + i*32)*EMB + ac);
    #pragma unroll
    for (int i = 0; i < 2; i++)
        Br[i] = *(const float4*)(Wq + (size_t)(br + i*16)*DKH + bc);

    for (int kc = 0; kc < EMB; kc += 32) {
        #pragma unroll
        for (int i = 0; i < 2; i++)
            *(uint4*)(As + (ar + i*32)*36 + ac) =
                make_uint4(f2tf(Ar[i].x), f2tf(Ar[i].y), f2tf(Ar[i].z), f2tf(Ar[i].w));
        #pragma unroll
        for (int i = 0; i < 2; i++)
            *(uint4*)(Bs + (br + i*16)*72 + bc) =
                make_uint4(f2tf(Br[i].x), f2tf(Br[i].y), f2tf(Br[i].z), f2tf(Br[i].w));
        __syncthreads();

        if (kc + 32 < EMB) {
            #pragma unroll
            for (int i = 0; i < 2; i++)
                Ar[i] = *(const float4*)(in2 + (size_t)(row0 + ar + i*32)*EMB + kc + 32 + ac);
            #pragma unroll
            for (int i = 0; i < 2; i++)
                Br[i] = *(const float4*)(Wq + (size_t)(kc + 32 + br + i*16)*DKH + bc);
        }

        #pragma unroll
        for (int ks = 0; ks < 4; ks++) {
            unsigned a[2][4];
            #pragma unroll
            for (int i = 0; i < 2; i++) {
                const unsigned* ap = As + (wm*32 + i*16 + g)*36 + ks*8 + tg;
                a[i][0] = ap[0]; a[i][1] = ap[8*36];
                a[i][2] = ap[4]; a[i][3] = ap[8*36 + 4];
            }
            unsigned bf[2][2];
            #pragma unroll
            for (int j = 0; j < 2; j++) {
                const unsigned* bp = Bs + (ks*8 + tg)*72 + wn*16 + j*8 + g;
                bf[j][0] = bp[0]; bf[j][1] = bp[4*72];
            }
            #pragma unroll
            for (int i = 0; i < 2; i++)
                #pragma unroll
                for (int j = 0; j < 2; j++)
                    mma8(acc[i][j], a[i][0], a[i][1], a[i][2], a[i][3],
                         bf[j][0], bf[j][1]);
        }
        __syncthreads();
    }
    const float QSCALE = 0.125f * 1.44269504088896340736f;
    store_proj64(g_Q, acc, bq, QSCALE, row0, wm, wn, g, tg);
}

// ============================================================================
// Kernel 1b: fused K+V projection, 64-row tiles (in1 read ONCE).
// grid = MTOT/64 = 256 CTAs, full SM coverage at 2 CTAs/SM.
// ============================================================================
__global__ __launch_bounds__(256) void proj_kv64(
    const float* __restrict__ in1,
    const float* __restrict__ Wk, const float* __restrict__ bk,
    const float* __restrict__ Wv, const float* __restrict__ bv)
{
    __shared__ unsigned As[64*36];
    __shared__ unsigned Bks[32*72];
    __shared__ unsigned Bvs[32*72];

    const int tid = threadIdx.x;
    const int lane = tid & 31, wid = tid >> 5;
    const int g = lane >> 2, tg = lane & 3;
    const int wm = wid & 1, wn = wid >> 1;
    const int row0 = blockIdx.x * 64;

    const int ar = tid >> 3,  ac = (tid & 7) * 4;
    const int br = tid >> 4,  bc = (tid & 15) * 4;

    float ak[2][2][4], av[2][2][4];
    #pragma unroll
    for (int i = 0; i < 2; i++)
        #pragma unroll
        for (int j = 0; j < 2; j++)
            #pragma unroll
            for (int e = 0; e < 4; e++) { ak[i][j][e] = 0.f; av[i][j][e] = 0.f; }

    float4 Ar[2], Bkr[2], Bvr[2];
    #pragma unroll
    for (int i = 0; i < 2; i++)
        Ar[i] = *(const float4*)(in1 + (size_t)(row0 + ar + i*32)*EMB + ac);
    #pragma unroll
    for (int i = 0; i < 2; i++) {
        Bkr[i] = *(const float4*)(Wk + (size_t)(br + i*16)*DKH + bc);
        Bvr[i] = *(const float4*)(Wv + (size_t)(br + i*16)*DKH + bc);
    }

    for (int kc = 0; kc < EMB; kc += 32) {
        #pragma unroll
        for (int i = 0; i < 2; i++)
            *(uint4*)(As + (ar + i*32)*36 + ac) =
                make_uint4(f2tf(Ar[i].x), f2tf(Ar[i].y), f2tf(Ar[i].z), f2tf(Ar[i].w));
        #pragma unroll
        for (int i = 0; i < 2; i++) {
            *(uint4*)(Bks + (br + i*16)*72 + bc) =
                make_uint4(f2tf(Bkr[i].x), f2tf(Bkr[i].y), f2tf(Bkr[i].z), f2tf(Bkr[i].w));
            *(uint4*)(Bvs + (br + i*16)*72 + bc) =
                make_uint4(f2tf(Bvr[i].x), f2tf(Bvr[i].y), f2tf(Bvr[i].z), f2tf(Bvr[i].w));
        }
        __syncthreads();

        if (kc + 32 < EMB) {
            #pragma unroll
            for (int i = 0; i < 2; i++)
                Ar[i] = *(const float4*)(in1 + (size_t)(row0 + ar + i*32)*EMB + kc + 32 + ac);
            #pragma unroll
            for (int i = 0; i < 2; i++) {
                Bkr[i] = *(const float4*)(Wk + (size_t)(kc + 32 + br + i*16)*DKH + bc);
                Bvr[i] = *(const float4*)(Wv + (size_t)(kc + 32 + br + i*16)*DKH + bc);
            }
        }

        #pragma unroll
        for (int ks = 0; ks < 4; ks++) {
            unsigned a[2][4];
            #pragma unroll
            for (int i = 0; i < 2; i++) {
                const unsigned* ap = As + (wm*32 + i*16 + g)*36 + ks*8 + tg;
                a[i][0] = ap[0]; a[i][1] = ap[8*36];
                a[i][2] = ap[4]; a[i][3] = ap[8*36 + 4];
            }
            unsigned fk[2][2], fv[2][2];
            #pragma unroll
            for (int j = 0; j < 2; j++) {
                const unsigned* kp = Bks + (ks*8 + tg)*72 + wn*16 + j*8 + g;
                fk[j][0] = kp[0]; fk[j][1] = kp[4*72];
                const unsigned* vp = Bvs + (ks*8 + tg)*72 + wn*16 + j*8 + g;
                fv[j][0] = vp[0]; fv[j][1] = vp[4*72];
            }
            #pragma unroll
            for (int i = 0; i < 2; i++)
                #pragma unroll
                for (int j = 0; j < 2; j++) {
                    mma8(ak[i][j], a[i][0], a[i][1], a[i][2], a[i][3],
                         fk[j][0], fk[j][1]);
                    mma8(av[i][j], a[i][0], a[i][1], a[i][2], a[i][3],
                         fv[j][0], fv[j][1]);
                }
        }
        __syncthreads();
    }
    store_proj64(g_K, ak, bk, 1.0f, row0, wm, wn, g, tg);
    store_proj64(g_V, av, bv, 1.0f, row0, wm, wn, g, tg);
}

// ============================================================================
// Kernel 2: flash attention, split-K=2 (UNCHANGED from R13, passing).
// grid = (SL/64, NB, NSPLIT) = 512 CTAs, 128 threads (4 warps x 16 q-rows).
// smem: K0,K1 (double-buffered), V (single), P = 69632B.
// ============================================================================
#define SK 68
#define KTW (64*SK)
#define SMEM_ATTN ((3*KTW + 4*16*SK) * 4)         // 69632 B

__global__ __launch_bounds__(128) void attn_kernel()
{
    extern __shared__ unsigned smem[];
    unsigned* Vs = smem + 2*KTW;
    unsigned* Ps = smem + 3*KTW;

    const int tid = threadIdx.x;
    const int lane = tid & 31, wid = tid >> 5;
    const int g = lane >> 2, tg = lane & 3;
    const int b = blockIdx.y;
    const int split = blockIdx.z;

    const unsigned* Qg = g_Q + ((size_t)b*SL + blockIdx.x*64 + wid*16) * DKH;
    const unsigned* Kg = g_K + ((size_t)b*SL + split*(SL/NSPLIT)) * DKH;
    const unsigned* Vg = g_V + ((size_t)b*SL + split*(SL/NSPLIT)) * DKH;
    unsigned* Pw = Ps + wid*16*SK;

    const int cr = tid >> 4, cc = (tid & 15) * 4;

    #pragma unroll
    for (int i = 0; i < 8; i++)
        cpa16(smem + (cr + i*8)*SK + cc, Kg + (size_t)(cr + i*8)*DKH + cc);
    asm volatile("cp.async.commit_group;");

    unsigned ql0[8], ql1[8], qh0[8], qh1[8];
    {
        const unsigned* q0 = Qg + (size_t)g * DKH;
        const unsigned* q1 = Qg + (size_t)(g + 8) * DKH;
        *(uint4*)(ql0)     = *(const uint4*)(q0 + tg*8);
        *(uint4*)(ql0 + 4) = *(const uint4*)(q0 + tg*8 + 4);
        *(uint4*)(qh0)     = *(const uint4*)(q0 + tg*8 + 32);
        *(uint4*)(qh0 + 4) = *(const uint4*)(q0 + tg*8 + 36);
        *(uint4*)(ql1)     = *(const uint4*)(q1 + tg*8);
        *(uint4*)(ql1 + 4) = *(const uint4*)(q1 + tg*8 + 4);
        *(uint4*)(qh1)     = *(const uint4*)(q1 + tg*8 + 32);
        *(uint4*)(qh1 + 4) = *(const uint4*)(q1 + tg*8 + 36);
    }

    float o[8][4];
    #pragma unroll
    for (int dt = 0; dt < 8; dt++)
        #pragma unroll
        for (int e = 0; e < 4; e++) o[dt][e] = 0.f;

    float m0 = -3.402823466e38f, m1 = -3.402823466e38f;
    float l0 = 0.f, l1 = 0.f;

    for (int t = 0; t < TPS; t++) {
        unsigned* Ks = smem + (t & 1) * KTW;
        const bool more = (t + 1 < TPS);

        {
            const unsigned* Vsrc = Vg + (size_t)t*64*DKH;
            #pragma unroll
            for (int i = 0; i < 8; i++)
                cpa16(Vs + (cr + i*8)*SK + cc, Vsrc + (size_t)(cr + i*8)*DKH + cc);
            asm volatile("cp.async.commit_group;");
        }
        if (more) {
            unsigned* Kn = smem + ((t + 1) & 1) * KTW;
            const unsigned* Ksrc = Kg + (size_t)(t + 1)*64*DKH;
            #pragma unroll
            for (int i = 0; i < 8; i++)
                cpa16(Kn + (cr + i*8)*SK + cc, Ksrc + (size_t)(cr + i*8)*DKH + cc);
            asm volatile("cp.async.commit_group;");
            asm volatile("cp.async.wait_group 2;");
        } else {
            asm volatile("cp.async.wait_group 1;");
        }
        __syncthreads();

        float s[8][4];
        #pragma unroll
        for (int nt = 0; nt < 8; nt++) {
            const unsigned* kb = Ks + (nt*8 + g)*SK + tg*8;
            unsigned kl[8], kh[8];
            *(uint4*)(kl)     = *(const uint4*)(kb);
            *(uint4*)(kl + 4) = *(const uint4*)(kb + 4);
            *(uint4*)(kh)     = *(const uint4*)(kb + 32);
            *(uint4*)(kh + 4) = *(const uint4*)(kb + 36);
            s[nt][0] = s[nt][1] = s[nt][2] = s[nt][3] = 0.f;
            #pragma unroll
            for (int dk = 0; dk < 8; dk++)
                mma8(s[nt], ql0[dk], ql1[dk], qh0[dk], qh1[dk], kl[dk], kh[dk]);
        }

        float mx0 = m0, mx1 = m1;
        #pragma unroll
        for (int nt = 0; nt < 8; nt++) {
            mx0 = fmaxf(mx0, fmaxf(s[nt][0], s[nt][1]));
            mx1 = fmaxf(mx1, fmaxf(s[nt][2], s[nt][3]));
        }
        mx0 = fmaxf(mx0, __shfl_xor_sync(0xffffffffu, mx0, 1));
        mx0 = fmaxf(mx0, __shfl_xor_sync(0xffffffffu, mx0, 2));
        mx1 = fmaxf(mx1, __shfl_xor_sync(0xffffffffu, mx1, 1));
        mx1 = fmaxf(mx1, __shfl_xor_sync(0xffffffffu, mx1, 2));

        float f0 = ex2(m0 - mx0);
        float f1 = ex2(m1 - mx1);

        float sum0 = 0.f, sum1 = 0.f;
        #pragma unroll
        for (int nt = 0; nt < 8; nt++) {
            s[nt][0] = ex2(s[nt][0] - mx0);
            s[nt][1] = ex2(s[nt][1] - mx0);
            s[nt][2] = ex2(s[nt][2] - mx1);
            s[nt][3] = ex2(s[nt][3] - mx1);
            sum0 += s[nt][0] + s[nt][1];
            sum1 += s[nt][2] + s[nt][3];
        }
        sum0 += __shfl_xor_sync(0xffffffffu, sum0, 1);
        sum0 += __shfl_xor_sync(0xffffffffu, sum0, 2);
        sum1 += __shfl_xor_sync(0xffffffffu, sum1, 1);
        sum1 += __shfl_xor_sync(0xffffffffu, sum1, 2);

        l0 = l0 * f0 + sum0;
        l1 = l1 * f1 + sum1;
        m0 = mx0; m1 = mx1;

        #pragma unroll
        for (int dt = 0; dt < 8; dt++) {
            o[dt][0] *= f0; o[dt][1] *= f0;
            o[dt][2] *= f1; o[dt][3] *= f1;
        }

        {
            unsigned* p0 = Pw + g*SK + 16*tg;
            *(uint4*)(p0)      = make_uint4(f2tf(s[0][0]), f2tf(s[1][0]), f2tf(s[2][0]), f2tf(s[3][0]));
            *(uint4*)(p0 + 4)  = make_uint4(f2tf(s[4][0]), f2tf(s[5][0]), f2tf(s[6][0]), f2tf(s[7][0]));
            *(uint4*)(p0 + 8)  = make_uint4(f2tf(s[0][1]), f2tf(s[1][1]), f2tf(s[2][1]), f2tf(s[3][1]));
            *(uint4*)(p0 + 12) = make_uint4(f2tf(s[4][1]), f2tf(s[5][1]), f2tf(s[6][1]), f2tf(s[7][1]));
            unsigned* p1 = Pw + (g + 8)*SK + 16*tg;
            *(uint4*)(p1)      = make_uint4(f2tf(s[0][2]), f2tf(s[1][2]), f2tf(s[2][2]), f2tf(s[3][2]));
            *(uint4*)(p1 + 4)  = make_uint4(f2tf(s[4][2]), f2tf(s[5][2]), f2tf(s[6][2]), f2tf(s[7][2]));
            *(uint4*)(p1 + 8)  = make_uint4(f2tf(s[0][3]), f2tf(s[1][3]), f2tf(s[2][3]), f2tf(s[3][3]));
            *(uint4*)(p1 + 12) = make_uint4(f2tf(s[4][3]), f2tf(s[5][3]), f2tf(s[6][3]), f2tf(s[7][3]));
        }
        __syncwarp();

        unsigned pl0[8], pl1[8], ph0[8], ph1[8];
        {
            const unsigned* pr0 = Pw + g*SK;
            const unsigned* pr1 = Pw + (g + 8)*SK;
            *(uint4*)(pl0)     = *(const uint4*)(pr0 + tg*8);
            *(uint4*)(pl0 + 4) = *(const uint4*)(pr0 + tg*8 + 4);
            *(uint4*)(ph0)     = *(const uint4*)(pr0 + tg*8 + 32);
            *(uint4*)(ph0 + 4) = *(const uint4*)(pr0 + tg*8 + 36);
            *(uint4*)(pl1)     = *(const uint4*)(pr1 + tg*8);
            *(uint4*)(pl1 + 4) = *(const uint4*)(pr1 + tg*8 + 4);
            *(uint4*)(ph1)     = *(const uint4*)(pr1 + tg*8 + 32);
            *(uint4*)(ph1 + 4) = *(const uint4*)(pr1 + tg*8 + 36);
        }

        if (more) asm volatile("cp.async.wait_group 1;");
        else      asm volatile("cp.async.wait_group 0;");
        __syncthreads();

        #pragma unroll
        for (int kk = 0; kk < 8; kk++) {
            const unsigned* vb0 = Vs + (kk*8 + tg)*SK + g*8;
            const unsigned* vb1 = vb0 + 4*SK;
            unsigned vl[8], vh[8];
            *(uint4*)(vl)     = *(const uint4*)(vb0);
            *(uint4*)(vl + 4) = *(const uint4*)(vb0 + 4);
            *(uint4*)(vh)     = *(const uint4*)(vb1);
            *(uint4*)(vh + 4) = *(const uint4*)(vb1 + 4);
            #pragma unroll
            for (int dt = 0; dt < 8; dt++)
                mma8(o[dt], pl0[kk], pl1[kk], ph0[kk], ph1[kk], vl[dt], vh[dt]);
        }
        __syncthreads();
    }

    size_t base = (size_t)split*MTOT + (size_t)b*SL + blockIdx.x*64 + wid*16;
    float* O0 = g_part + (base + g) * DKH;
    float* O1 = g_part + (base + g + 8) * DKH;
    #pragma unroll
    for (int dt = 0; dt < 8; dt++) {
        int c = dt*8 + 2*tg;
        *(float2*)(O0 + c) = make_float2(o[dt][0], o[dt][1]);
        *(float2*)(O1 + c) = make_float2(o[dt][2], o[dt][3]);
    }
    if (tg == 0) {
        g_ml[(base + g)*2]         = m0;
        g_ml[(base + g)*2 + 1]     = l0;
        g_ml[(base + g + 8)*2]     = m1;
        g_ml[(base + g + 8)*2 + 1] = l1;
    }
}

// ============================================================================
// Kernel 3: split merge (UNCHANGED, validated).
// ============================================================================
__global__ __launch_bounds__(256) void merge_kernel(float* __restrict__ out)
{
    int t = blockIdx.x * 256 + threadIdx.x;
    int row = t >> 5;
    int cp  = (t & 31) * 2;

    float m[NSPLIT], l[NSPLIT];
    #pragma unroll
    for (int s = 0; s < NSPLIT; s++) {
        m[s] = g_ml[((size_t)s*MTOT + row)*2];
        l[s] = g_ml[((size_t)s*MTOT + row)*2 + 1];
    }
    float M = m[0];
    #pragma unroll
    for (int s = 1; s < NSPLIT; s++) M = fmaxf(M, m[s]);
    float w[NSPLIT], L = 0.f;
    #pragma unroll
    for (int s = 0; s < NSPLIT; s++) { w[s] = ex2(m[s] - M); L += w[s]*l[s]; }

    float ax = 0.f, ay = 0.f;
    #pragma unroll
    for (int s = 0; s < NSPLIT; s++) {
        float2 v = *(const float2*)(g_part + ((size_t)s*MTOT + row)*DKH + cp);
        ax += w[s]*v.x; ay += w[s]*v.y;
    }
    float invL = 1.f / L;
    *(float2*)(out + (size_t)row*DKH + cp) = make_float2(ax*invL, ay*invL);
}

// ============================================================================
extern "C" void kernel_launch(void* const* d_in, const int* in_sizes, int n_in,
                              void* d_out, int out_size)
{
    const float* in1 = (const float*)d_in[0];
    const float* in2 = (const float*)d_in[1];
    const float* Wq  = (const float*)d_in[2];
    const float* bq  = (const float*)d_in[3];
    const float* Wk  = (const float*)d_in[4];
    const float* bk  = (const float*)d_in[5];
    const float* Wv  = (const float*)d_in[6];
    const float* bv  = (const float*)d_in[7];
    float* out = (float*)d_out;

    cudaFuncSetAttribute(attn_kernel,
                         cudaFuncAttributeMaxDynamicSharedMemorySize, SMEM_ATTN);

    proj_q64 <<<MTOT/64, 256>>>(in2, Wq, bq);
    proj_kv64<<<MTOT/64, 256>>>(in1, Wk, bk, Wv, bv);
    attn_kernel<<<dim3(SL/64, NB, NSPLIT), 128, SMEM_ATTN>>>();
    merge_kernel<<<(MTOT*32)/256, 256>>>(out);
}

// round 16
// speedup vs baseline: 1.0429x; 1.0429x over previous
#include <cuda_runtime.h>

#define EMB 1024
#define DKH 64
#define NB 4
#define SL 4096
#define MTOT (NB*SL)
#define NSPLIT 2
#define TPS (SL/64/NSPLIT)     // key tiles per split = 32

// ---------------- scratch (no allocations allowed) ----------------
// Q/K/V stored as tf32 bits, d-transposed within each 64-wide row:
//   element (row, d) lives at word  row*64 + (d%8)*8 + d/8
__device__ unsigned g_Q[MTOT*DKH];
__device__ unsigned g_K[MTOT*DKH];
__device__ unsigned g_V[MTOT*DKH];
__device__ float    g_part[(size_t)NSPLIT*MTOT*DKH];  // unnormalized partial O
__device__ float    g_ml[(size_t)NSPLIT*MTOT*2];      // (m, l) per split per row

// ---------------- helpers ----------------
__device__ __forceinline__ unsigned f2tf(float f){
    unsigned u; asm("cvt.rna.tf32.f32 %0, %1;" : "=r"(u) : "f"(f)); return u;
}
__device__ __forceinline__ float ex2(float x){
    float y; asm("ex2.approx.ftz.f32 %0, %1;" : "=f"(y) : "f"(x)); return y;
}
__device__ __forceinline__ void mma8(float* c,
        unsigned a0, unsigned a1, unsigned a2, unsigned a3,
        unsigned b0, unsigned b1){
    asm volatile(
        "mma.sync.aligned.m16n8k8.row.col.f32.tf32.tf32.f32 "
        "{%0,%1,%2,%3},{%4,%5,%6,%7},{%8,%9},{%0,%1,%2,%3};"
        : "+f"(c[0]), "+f"(c[1]), "+f"(c[2]), "+f"(c[3])
        : "r"(a0), "r"(a1), "r"(a2), "r"(a3), "r"(b0), "r"(b1));
}
__device__ __forceinline__ void cpa16(void* s, const void* g){
    asm volatile("cp.async.cg.shared.global [%0], [%1], 16;"
        :: "r"((unsigned)__cvta_generic_to_shared(s)), "l"(g));
}

// 128-row-tile epilogue: bias + scale, tf32 convert, d-transposed layout
// (VALIDATED in R12/R13).  word(row,d) = row*64 + 16tg + 4wn + j (+8 odd d).
__device__ __forceinline__ void store_proj(unsigned* out, float acc[2][4][4],
        const float* __restrict__ bias, float scale,
        int row0, int wm, int wn, int g, int tg)
{
    #pragma unroll
    for (int i = 0; i < 2; i++) {
        int r0 = row0 + wm*32 + i*16 + g;
        unsigned lo0[4], hi0[4], lo1[4], hi1[4];
        #pragma unroll
        for (int j = 0; j < 4; j++) {
            int c = wn*32 + j*8 + 2*tg;
            float b0 = bias[c], b1 = bias[c+1];
            lo0[j] = f2tf((acc[i][j][0] + b0) * scale);
            hi0[j] = f2tf((acc[i][j][1] + b1) * scale);
            lo1[j] = f2tf((acc[i][j][2] + b0) * scale);
            hi1[j] = f2tf((acc[i][j][3] + b1) * scale);
        }
        unsigned* p0 = out + (size_t)r0 * DKH + 16*tg + 4*wn;
        *(uint4*)(p0)     = make_uint4(lo0[0], lo0[1], lo0[2], lo0[3]);
        *(uint4*)(p0 + 8) = make_uint4(hi0[0], hi0[1], hi0[2], hi0[3]);
        unsigned* p1 = out + (size_t)(r0 + 8) * DKH + 16*tg + 4*wn;
        *(uint4*)(p1)     = make_uint4(lo1[0], lo1[1], lo1[2], lo1[3]);
        *(uint4*)(p1 + 8) = make_uint4(hi1[0], hi1[1], hi1[2], hi1[3]);
    }
}

// ============================================================================
// Kernel 1: QKV projection with 3-stage cp.async pipeline (f32 in smem,
// tf32 convert at fragment load — numerically identical to store-side cvt).
// blockIdx.y = 0/1/2 -> Q/K/V.  grid (128, 3) = 384 CTAs, 256 threads.
// smem: 3 stages x (A 128x36 + B 32x72) f32 = 82944 B -> 2 CTAs/SM.
// ============================================================================
#define ASTR 36
#define BSTR 72
#define STG_WORDS (128*ASTR + 32*BSTR)          // 6912
#define NCHUNK (EMB/32)                          // 32
#define SMEM_PROJ (3*STG_WORDS*4)                // 82944 B

__global__ __launch_bounds__(256) void proj_kernel(
    const float* __restrict__ in1, const float* __restrict__ in2,
    const float* __restrict__ Wq, const float* __restrict__ bq,
    const float* __restrict__ Wk, const float* __restrict__ bk,
    const float* __restrict__ Wv, const float* __restrict__ bv)
{
    extern __shared__ float psm[];

    const int tid = threadIdx.x;
    const int lane = tid & 31, wid = tid >> 5;
    const int g = lane >> 2, tg = lane & 3;
    const int wm = wid & 3, wn = wid >> 2;      // 4 x 2 warps over 128x64
    const int row0 = blockIdx.x * 128;

    const int sel = blockIdx.y;
    const float* A    = (sel == 0) ? in2 : in1;
    const float* W    = (sel == 0) ? Wq : (sel == 1 ? Wk : Wv);
    const float* bias = (sel == 0) ? bq : (sel == 1 ? bk : bv);
    unsigned* out = (sel == 0) ? g_Q : (sel == 1 ? g_K : g_V);
    const float scale = (sel == 0) ? 0.125f * 1.44269504088896340736f : 1.0f;

    // cp.async coordinates (16B quads)
    const int ar = tid >> 3,  ac = (tid & 7) * 4;     // A: +i*32 rows, 4 quads/thread
    const int br = tid >> 4,  bc = (tid & 15) * 4;    // B: +i*16 rows, 2 quads/thread

    float acc[2][4][4];
    #pragma unroll
    for (int i = 0; i < 2; i++)
        #pragma unroll
        for (int j = 0; j < 4; j++)
            #pragma unroll
            for (int e = 0; e < 4; e++) acc[i][j][e] = 0.f;

    // ---- prologue: stream chunks 0,1,2 into stages 0,1,2 ----
    #pragma unroll
    for (int s = 0; s < 3; s++) {
        float* Af = psm + s*STG_WORDS;
        float* Bf = Af + 128*ASTR;
        const int kc = s*32;
        #pragma unroll
        for (int i = 0; i < 4; i++)
            cpa16(Af + (ar + i*32)*ASTR + ac,
                  A + (size_t)(row0 + ar + i*32)*EMB + kc + ac);
        #pragma unroll
        for (int i = 0; i < 2; i++)
            cpa16(Bf + (br + i*16)*BSTR + bc,
                  W + (size_t)(kc + br + i*16)*DKH + bc);
        asm volatile("cp.async.commit_group;");
    }

    for (int t = 0; t < NCHUNK; t++) {
        asm volatile("cp.async.wait_group 2;");   // chunk t resident
        __syncthreads();

        const float* Af = psm + (t % 3)*STG_WORDS;
        const float* Bf = Af + 128*ASTR;

        // ---- compute: 4 k-steps x 8 mmas, cvt at frag load ----
        #pragma unroll
        for (int ks = 0; ks < 4; ks++) {
            unsigned a[2][4];
            #pragma unroll
            for (int i = 0; i < 2; i++) {
                const float* ap = Af + (wm*32 + i*16 + g)*ASTR + ks*8 + tg;
                a[i][0] = f2tf(ap[0]);
                a[i][1] = f2tf(ap[8*ASTR]);
                a[i][2] = f2tf(ap[4]);
                a[i][3] = f2tf(ap[8*ASTR + 4]);
            }
            unsigned bf[4][2];
            #pragma unroll
            for (int j = 0; j < 4; j++) {
                const float* bp = Bf + (ks*8 + tg)*BSTR + wn*32 + j*8 + g;
                bf[j][0] = f2tf(bp[0]);
                bf[j][1] = f2tf(bp[4*BSTR]);
            }
            #pragma unroll
            for (int i = 0; i < 2; i++)
                #pragma unroll
                for (int j = 0; j < 4; j++)
                    mma8(acc[i][j], a[i][0], a[i][1], a[i][2], a[i][3],
                         bf[j][0], bf[j][1]);
        }
        __syncthreads();   // all warps done with stage t%3

        // ---- stream chunk t+3 into the freed stage; commit every iter ----
        if (t + 3 < NCHUNK) {
            float* An = psm + (t % 3)*STG_WORDS;
            float* Bn = An + 128*ASTR;
            const int kc = (t + 3)*32;
            #pragma unroll
            for (int i = 0; i < 4; i++)
                cpa16(An + (ar + i*32)*ASTR + ac,
                      A + (size_t)(row0 + ar + i*32)*EMB + kc + ac);
            #pragma unroll
            for (int i = 0; i < 2; i++)
                cpa16(Bn + (br + i*16)*BSTR + bc,
                      W + (size_t)(kc + br + i*16)*DKH + bc);
        }
        asm volatile("cp.async.commit_group;");   // (possibly empty) keeps group count uniform
    }
    store_proj(out, acc, bias, scale, row0, wm, wn, g, tg);
}

// ============================================================================
// Kernel 2: flash attention, split-K=2 (UNCHANGED — passing, validated).
// grid = (SL/64, NB, NSPLIT) = 512 CTAs, 128 threads (4 warps x 16 q-rows).
// smem: K0,K1 (double-buffered), V (single), P = 69632B.
// ============================================================================
#define SK 68
#define KTW (64*SK)
#define SMEM_ATTN ((3*KTW + 4*16*SK) * 4)         // 69632 B

__global__ __launch_bounds__(128) void attn_kernel()
{
    extern __shared__ unsigned smem[];
    unsigned* Vs = smem + 2*KTW;
    unsigned* Ps = smem + 3*KTW;

    const int tid = threadIdx.x;
    const int lane = tid & 31, wid = tid >> 5;
    const int g = lane >> 2, tg = lane & 3;
    const int b = blockIdx.y;
    const int split = blockIdx.z;

    const unsigned* Qg = g_Q + ((size_t)b*SL + blockIdx.x*64 + wid*16) * DKH;
    const unsigned* Kg = g_K + ((size_t)b*SL + split*(SL/NSPLIT)) * DKH;
    const unsigned* Vg = g_V + ((size_t)b*SL + split*(SL/NSPLIT)) * DKH;
    unsigned* Pw = Ps + wid*16*SK;

    const int cr = tid >> 4, cc = (tid & 15) * 4;

    #pragma unroll
    for (int i = 0; i < 8; i++)
        cpa16(smem + (cr + i*8)*SK + cc, Kg + (size_t)(cr + i*8)*DKH + cc);
    asm volatile("cp.async.commit_group;");

    unsigned ql0[8], ql1[8], qh0[8], qh1[8];
    {
        const unsigned* q0 = Qg + (size_t)g * DKH;
        const unsigned* q1 = Qg + (size_t)(g + 8) * DKH;
        *(uint4*)(ql0)     = *(const uint4*)(q0 + tg*8);
        *(uint4*)(ql0 + 4) = *(const uint4*)(q0 + tg*8 + 4);
        *(uint4*)(qh0)     = *(const uint4*)(q0 + tg*8 + 32);
        *(uint4*)(qh0 + 4) = *(const uint4*)(q0 + tg*8 + 36);
        *(uint4*)(ql1)     = *(const uint4*)(q1 + tg*8);
        *(uint4*)(ql1 + 4) = *(const uint4*)(q1 + tg*8 + 4);
        *(uint4*)(qh1)     = *(const uint4*)(q1 + tg*8 + 32);
        *(uint4*)(qh1 + 4) = *(const uint4*)(q1 + tg*8 + 36);
    }

    float o[8][4];
    #pragma unroll
    for (int dt = 0; dt < 8; dt++)
        #pragma unroll
        for (int e = 0; e < 4; e++) o[dt][e] = 0.f;

    float m0 = -3.402823466e38f, m1 = -3.402823466e38f;
    float l0 = 0.f, l1 = 0.f;

    for (int t = 0; t < TPS; t++) {
        unsigned* Ks = smem + (t & 1) * KTW;
        const bool more = (t + 1 < TPS);

        {
            const unsigned* Vsrc = Vg + (size_t)t*64*DKH;
            #pragma unroll
            for (int i = 0; i < 8; i++)
                cpa16(Vs + (cr + i*8)*SK + cc, Vsrc + (size_t)(cr + i*8)*DKH + cc);
            asm volatile("cp.async.commit_group;");
        }
        if (more) {
            unsigned* Kn = smem + ((t + 1) & 1) * KTW;
            const unsigned* Ksrc = Kg + (size_t)(t + 1)*64*DKH;
            #pragma unroll
            for (int i = 0; i < 8; i++)
                cpa16(Kn + (cr + i*8)*SK + cc, Ksrc + (size_t)(cr + i*8)*DKH + cc);
            asm volatile("cp.async.commit_group;");
            asm volatile("cp.async.wait_group 2;");
        } else {
            asm volatile("cp.async.wait_group 1;");
        }
        __syncthreads();

        float s[8][4];
        #pragma unroll
        for (int nt = 0; nt < 8; nt++) {
            const unsigned* kb = Ks + (nt*8 + g)*SK + tg*8;
            unsigned kl[8], kh[8];
            *(uint4*)(kl)     = *(const uint4*)(kb);
            *(uint4*)(kl + 4) = *(const uint4*)(kb + 4);
            *(uint4*)(kh)     = *(const uint4*)(kb + 32);
            *(uint4*)(kh + 4) = *(const uint4*)(kb + 36);
            s[nt][0] = s[nt][1] = s[nt][2] = s[nt][3] = 0.f;
            #pragma unroll
            for (int dk = 0; dk < 8; dk++)
                mma8(s[nt], ql0[dk], ql1[dk], qh0[dk], qh1[dk], kl[dk], kh[dk]);
        }

        float mx0 = m0, mx1 = m1;
        #pragma unroll
        for (int nt = 0; nt < 8; nt++) {
            mx0 = fmaxf(mx0, fmaxf(s[nt][0], s[nt][1]));
            mx1 = fmaxf(mx1, fmaxf(s[nt][2], s[nt][3]));
        }
        mx0 = fmaxf(mx0, __shfl_xor_sync(0xffffffffu, mx0, 1));
        mx0 = fmaxf(mx0, __shfl_xor_sync(0xffffffffu, mx0, 2));
        mx1 = fmaxf(mx1, __shfl_xor_sync(0xffffffffu, mx1, 1));
        mx1 = fmaxf(mx1, __shfl_xor_sync(0xffffffffu, mx1, 2));

        float f0 = ex2(m0 - mx0);
        float f1 = ex2(m1 - mx1);

        float sum0 = 0.f, sum1 = 0.f;
        #pragma unroll
        for (int nt = 0; nt < 8; nt++) {
            s[nt][0] = ex2(s[nt][0] - mx0);
            s[nt][1] = ex2(s[nt][1] - mx0);
            s[nt][2] = ex2(s[nt][2] - mx1);
            s[nt][3] = ex2(s[nt][3] - mx1);
            sum0 += s[nt][0] + s[nt][1];
            sum1 += s[nt][2] + s[nt][3];
        }
        sum0 += __shfl_xor_sync(0xffffffffu, sum0, 1);
        sum0 += __shfl_xor_sync(0xffffffffu, sum0, 2);
        sum1 += __shfl_xor_sync(0xffffffffu, sum1, 1);
        sum1 += __shfl_xor_sync(0xffffffffu, sum1, 2);

        l0 = l0 * f0 + sum0;
        l1 = l1 * f1 + sum1;
        m0 = mx0; m1 = mx1;

        #pragma unroll
        for (int dt = 0; dt < 8; dt++) {
            o[dt][0] *= f0; o[dt][1] *= f0;
            o[dt][2] *= f1; o[dt][3] *= f1;
        }

        {
            unsigned* p0 = Pw + g*SK + 16*tg;
            *(uint4*)(p0)      = make_uint4(f2tf(s[0][0]), f2tf(s[1][0]), f2tf(s[2][0]), f2tf(s[3][0]));
            *(uint4*)(p0 + 4)  = make_uint4(f2tf(s[4][0]), f2tf(s[5][0]), f2tf(s[6][0]), f2tf(s[7][0]));
            *(uint4*)(p0 + 8)  = make_uint4(f2tf(s[0][1]), f2tf(s[1][1]), f2tf(s[2][1]), f2tf(s[3][1]));
            *(uint4*)(p0 + 12) = make_uint4(f2tf(s[4][1]), f2tf(s[5][1]), f2tf(s[6][1]), f2tf(s[7][1]));
            unsigned* p1 = Pw + (g + 8)*SK + 16*tg;
            *(uint4*)(p1)      = make_uint4(f2tf(s[0][2]), f2tf(s[1][2]), f2tf(s[2][2]), f2tf(s[3][2]));
            *(uint4*)(p1 + 4)  = make_uint4(f2tf(s[4][2]), f2tf(s[5][2]), f2tf(s[6][2]), f2tf(s[7][2]));
            *(uint4*)(p1 + 8)  = make_uint4(f2tf(s[0][3]), f2tf(s[1][3]), f2tf(s[2][3]), f2tf(s[3][3]));
            *(uint4*)(p1 + 12) = make_uint4(f2tf(s[4][3]), f2tf(s[5][3]), f2tf(s[6][3]), f2tf(s[7][3]));
        }
        __syncwarp();

        unsigned pl0[8], pl1[8], ph0[8], ph1[8];
        {
            const unsigned* pr0 = Pw + g*SK;
            const unsigned* pr1 = Pw + (g + 8)*SK;
            *(uint4*)(pl0)     = *(const uint4*)(pr0 + tg*8);
            *(uint4*)(pl0 + 4) = *(const uint4*)(pr0 + tg*8 + 4);
            *(uint4*)(ph0)     = *(const uint4*)(pr0 + tg*8 + 32);
            *(uint4*)(ph0 + 4) = *(const uint4*)(pr0 + tg*8 + 36);
            *(uint4*)(pl1)     = *(const uint4*)(pr1 + tg*8);
            *(uint4*)(pl1 + 4) = *(const uint4*)(pr1 + tg*8 + 4);
            *(uint4*)(ph1)     = *(const uint4*)(pr1 + tg*8 + 32);
            *(uint4*)(ph1 + 4) = *(const uint4*)(pr1 + tg*8 + 36);
        }

        if (more) asm volatile("cp.async.wait_group 1;");
        else      asm volatile("cp.async.wait_group 0;");
        __syncthreads();

        #pragma unroll
        for (int kk = 0; kk < 8; kk++) {
            const unsigned* vb0 = Vs + (kk*8 + tg)*SK + g*8;
            const unsigned* vb1 = vb0 + 4*SK;
            unsigned vl[8], vh[8];
            *(uint4*)(vl)     = *(const uint4*)(vb0);
            *(uint4*)(vl + 4) = *(const uint4*)(vb0 + 4);
            *(uint4*)(vh)     = *(const uint4*)(vb1);
            *(uint4*)(vh + 4) = *(const uint4*)(vb1 + 4);
            #pragma unroll
            for (int dt = 0; dt < 8; dt++)
                mma8(o[dt], pl0[kk], pl1[kk], ph0[kk], ph1[kk], vl[dt], vh[dt]);
        }
        __syncthreads();
    }

    size_t base = (size_t)split*MTOT + (size_t)b*SL + blockIdx.x*64 + wid*16;
    float* O0 = g_part + (base + g) * DKH;
    float* O1 = g_part + (base + g + 8) * DKH;
    #pragma unroll
    for (int dt = 0; dt < 8; dt++) {
        int c = dt*8 + 2*tg;
        *(float2*)(O0 + c) = make_float2(o[dt][0], o[dt][1]);
        *(float2*)(O1 + c) = make_float2(o[dt][2], o[dt][3]);
    }
    if (tg == 0) {
        g_ml[(base + g)*2]         = m0;
        g_ml[(base + g)*2 + 1]     = l0;
        g_ml[(base + g + 8)*2]     = m1;
        g_ml[(base + g + 8)*2 + 1] = l1;
    }
}

// ============================================================================
// Kernel 3: split merge (UNCHANGED, validated).
// ============================================================================
__global__ __launch_bounds__(256) void merge_kernel(float* __restrict__ out)
{
    int t = blockIdx.x * 256 + threadIdx.x;
    int row = t >> 5;
    int cp  = (t & 31) * 2;

    float m[NSPLIT], l[NSPLIT];
    #pragma unroll
    for (int s = 0; s < NSPLIT; s++) {
        m[s] = g_ml[((size_t)s*MTOT + row)*2];
        l[s] = g_ml[((size_t)s*MTOT + row)*2 + 1];
    }
    float M = m[0];
    #pragma unroll
    for (int s = 1; s < NSPLIT; s++) M = fmaxf(M, m[s]);
    float w[NSPLIT], L = 0.f;
    #pragma unroll
    for (int s = 0; s < NSPLIT; s++) { w[s] = ex2(m[s] - M); L += w[s]*l[s]; }

    float ax = 0.f, ay = 0.f;
    #pragma unroll
    for (int s = 0; s < NSPLIT; s++) {
        float2 v = *(const float2*)(g_part + ((size_t)s*MTOT + row)*DKH + cp);
        ax += w[s]*v.x; ay += w[s]*v.y;
    }
    float invL = 1.f / L;
    *(float2*)(out + (size_t)row*DKH + cp) = make_float2(ax*invL, ay*invL);
}

// ============================================================================
extern "C" void kernel_launch(void* const* d_in, const int* in_sizes, int n_in,
                              void* d_out, int out_size)
{
    const float* in1 = (const float*)d_in[0];
    const float* in2 = (const float*)d_in[1];
    const float* Wq  = (const float*)d_in[2];
    const float* bq  = (const float*)d_in[3];
    const float* Wk  = (const float*)d_in[4];
    const float* bk  = (const float*)d_in[5];
    const float* Wv  = (const float*)d_in[6];
    const float* bv  = (const float*)d_in[7];
    float* out = (float*)d_out;

    cudaFuncSetAttribute(proj_kernel,
                         cudaFuncAttributeMaxDynamicSharedMemorySize, SMEM_PROJ);
    cudaFuncSetAttribute(attn_kernel,
                         cudaFuncAttributeMaxDynamicSharedMemorySize, SMEM_ATTN);

    proj_kernel<<<dim3(MTOT/128, 3), 256, SMEM_PROJ>>>(in1, in2, Wq, bq, Wk, bk, Wv, bv);
    attn_kernel<<<dim3(SL/64, NB, NSPLIT), 128, SMEM_ATTN>>>();
    merge_kernel<<<(MTOT*32)/256, 256>>>(out);
}